// round 1
// baseline (speedup 1.0000x reference)
#include <cuda_runtime.h>

#define N_NODES 100000
#define N_EDGES 1600000
#define IN_CH   128
#define HID     64

// ---------------- device scratch (no allocations allowed) ----------------
__device__ int   g_deg[N_NODES];
__device__ int   g_off[N_NODES + 1];
__device__ int   g_cursor[N_NODES];
__device__ int   g_ssrc[N_EDGES];
__device__ int   g_bsum[128];
__device__ int   g_boff[128];
__device__ float g_hw[N_NODES * HID];   // transformed features (gather source)
__device__ float g_h [N_NODES * HID];   // aggregated features

// ---------------- CSR build ----------------
__global__ void k_zero_deg() {
    int i = blockIdx.x * blockDim.x + threadIdx.x;
    if (i < N_NODES) g_deg[i] = 0;
}

__global__ void k_hist(const int* __restrict__ dst) {
    int i = blockIdx.x * blockDim.x + threadIdx.x;
    if (i < N_EDGES) atomicAdd(&g_deg[dst[i]], 1);
}

__global__ void k_scan_blocks() {
    __shared__ int s[1024];
    int tid = threadIdx.x;
    int i = blockIdx.x * 1024 + tid;
    int v = (i < N_NODES) ? g_deg[i] : 0;
    s[tid] = v;
    __syncthreads();
    #pragma unroll
    for (int off = 1; off < 1024; off <<= 1) {
        int t = (tid >= off) ? s[tid - off] : 0;
        __syncthreads();
        s[tid] += t;
        __syncthreads();
    }
    if (i < N_NODES) g_off[i] = s[tid] - v;   // block-local exclusive
    if (tid == 1023) g_bsum[blockIdx.x] = s[1023];
}

__global__ void k_scan_top(int nb) {
    if (threadIdx.x == 0) {
        int run = 0;
        for (int b = 0; b < nb; b++) { g_boff[b] = run; run += g_bsum[b]; }
    }
}

__global__ void k_scan_add() {
    int i = blockIdx.x * blockDim.x + threadIdx.x;
    if (i < N_NODES) {
        int o = g_off[i] + g_boff[i >> 10];
        g_off[i] = o;
        g_cursor[i] = o;
    }
    if (i == 0) g_off[N_NODES] = N_EDGES;
}

__global__ void k_scatter(const int* __restrict__ src, const int* __restrict__ dst) {
    int i = blockIdx.x * blockDim.x + threadIdx.x;
    if (i < N_EDGES) {
        int p = atomicAdd(&g_cursor[dst[i]], 1);
        g_ssrc[p] = src[i];
    }
}

// ---------------- dense transform: O[n,64] = X[n,K] @ W[K,64] ----------------
// 256 threads/block, 64 rows/block; each thread: 2 rows x 8 cols.
template <int K>
__global__ __launch_bounds__(256)
void k_transform(const float* __restrict__ X, const float* __restrict__ W,
                 float* __restrict__ O) {
    extern __shared__ float sm[];
    float* sW = sm;               // K*64
    float* sX = sm + K * 64;      // 64*(K+1)  (padded rows: no bank conflicts)
    const int tid = threadIdx.x;

    for (int i = tid; i < K * 64; i += 256) sW[i] = W[i];

    int rowBase = blockIdx.x * 64;
    for (int i = tid; i < 64 * K; i += 256) {
        int r = i / K, k = i - r * K;
        int gr = rowBase + r;
        sX[r * (K + 1) + k] = (gr < N_NODES) ? X[gr * K + k] : 0.f;
    }
    __syncthreads();

    const int colq = (tid & 7) * 8;        // 8 contiguous output cols
    const int r0 = (tid >> 3) * 2;         // 2 rows
    const int r1 = r0 + 1;
    const float* x0 = &sX[r0 * (K + 1)];
    const float* x1 = &sX[r1 * (K + 1)];

    float a0[8], a1[8];
    #pragma unroll
    for (int j = 0; j < 8; j++) { a0[j] = 0.f; a1[j] = 0.f; }

    #pragma unroll 16
    for (int k = 0; k < K; k++) {
        float4 wA = *(const float4*)&sW[k * 64 + colq];
        float4 wB = *(const float4*)&sW[k * 64 + colq + 4];
        float p0 = x0[k];
        float p1 = x1[k];
        a0[0] += p0 * wA.x; a0[1] += p0 * wA.y; a0[2] += p0 * wA.z; a0[3] += p0 * wA.w;
        a0[4] += p0 * wB.x; a0[5] += p0 * wB.y; a0[6] += p0 * wB.z; a0[7] += p0 * wB.w;
        a1[0] += p1 * wA.x; a1[1] += p1 * wA.y; a1[2] += p1 * wA.z; a1[3] += p1 * wA.w;
        a1[4] += p1 * wB.x; a1[5] += p1 * wB.y; a1[6] += p1 * wB.z; a1[7] += p1 * wB.w;
    }

    int gr0 = rowBase + r0, gr1 = rowBase + r1;
    if (gr0 < N_NODES) {
        *(float4*)&O[gr0 * 64 + colq]     = make_float4(a0[0], a0[1], a0[2], a0[3]);
        *(float4*)&O[gr0 * 64 + colq + 4] = make_float4(a0[4], a0[5], a0[6], a0[7]);
    }
    if (gr1 < N_NODES) {
        *(float4*)&O[gr1 * 64 + colq]     = make_float4(a1[0], a1[1], a1[2], a1[3]);
        *(float4*)&O[gr1 * 64 + colq + 4] = make_float4(a1[4], a1[5], a1[6], a1[7]);
    }
}

// ---------------- CSR gather-sum aggregation: one warp per node ----------------
template <bool RELU>
__global__ __launch_bounds__(256)
void k_agg(const float* __restrict__ HW, const float* __restrict__ bias,
           float* __restrict__ O) {
    int warp = (blockIdx.x * blockDim.x + threadIdx.x) >> 5;
    int lane = threadIdx.x & 31;
    if (warp >= N_NODES) return;

    int start = g_off[warp];
    int end   = g_off[warp + 1];

    const float2* __restrict__ hw2 = (const float2*)HW;
    float2 a0 = {0.f, 0.f}, a1 = {0.f, 0.f}, a2 = {0.f, 0.f}, a3 = {0.f, 0.f};

    int e = start;
    for (; e + 4 <= end; e += 4) {
        int s0 = __ldg(&g_ssrc[e]);
        int s1 = __ldg(&g_ssrc[e + 1]);
        int s2 = __ldg(&g_ssrc[e + 2]);
        int s3 = __ldg(&g_ssrc[e + 3]);
        float2 v0 = __ldg(&hw2[s0 * 32 + lane]);
        float2 v1 = __ldg(&hw2[s1 * 32 + lane]);
        float2 v2 = __ldg(&hw2[s2 * 32 + lane]);
        float2 v3 = __ldg(&hw2[s3 * 32 + lane]);
        a0.x += v0.x; a0.y += v0.y;
        a1.x += v1.x; a1.y += v1.y;
        a2.x += v2.x; a2.y += v2.y;
        a3.x += v3.x; a3.y += v3.y;
    }
    for (; e < end; e++) {
        int s = __ldg(&g_ssrc[e]);
        float2 v = __ldg(&hw2[s * 32 + lane]);
        a0.x += v.x; a0.y += v.y;
    }

    float2 b = __ldg(&((const float2*)bias)[lane]);
    float rx = (a0.x + a1.x) + (a2.x + a3.x) + b.x;
    float ry = (a0.y + a1.y) + (a2.y + a3.y) + b.y;
    if (RELU) { rx = fmaxf(rx, 0.f); ry = fmaxf(ry, 0.f); }
    ((float2*)O)[warp * 32 + lane] = make_float2(rx, ry);
}

// ---------------- launch ----------------
extern "C" void kernel_launch(void* const* d_in, const int* in_sizes, int n_in,
                              void* d_out, int out_size) {
    const float* x    = (const float*)d_in[0];
    const int*   esrc = (const int*)  d_in[1];
    const int*   edst = (const int*)  d_in[2];
    const float* W1   = (const float*)d_in[3];
    const float* b1   = (const float*)d_in[4];
    const float* W2   = (const float*)d_in[5];
    const float* b2   = (const float*)d_in[6];
    const float* W3   = (const float*)d_in[7];
    const float* b3   = (const float*)d_in[8];
    float* out = (float*)d_out;

    void* p_hw_v; cudaGetSymbolAddress(&p_hw_v, g_hw);
    void* p_h_v;  cudaGetSymbolAddress(&p_h_v,  g_h);
    float* p_hw = (float*)p_hw_v;
    float* p_h  = (float*)p_h_v;

    const int smem128 = (128 * 64 + 64 * 129) * 4;   // 65,792 B
    const int smem64  = (64 * 64 + 64 * 65) * 4;     // 33,024 B
    cudaFuncSetAttribute(k_transform<128>, cudaFuncAttributeMaxDynamicSharedMemorySize, smem128);
    cudaFuncSetAttribute(k_transform<64>,  cudaFuncAttributeMaxDynamicSharedMemorySize, smem64);

    // ---- CSR build (per launch: deterministic work) ----
    k_zero_deg<<<(N_NODES + 255) / 256, 256>>>();
    k_hist<<<(N_EDGES + 255) / 256, 256>>>(edst);
    int nb = (N_NODES + 1023) / 1024;
    k_scan_blocks<<<nb, 1024>>>();
    k_scan_top<<<1, 32>>>(nb);
    k_scan_add<<<(N_NODES + 255) / 256, 256>>>();
    k_scatter<<<(N_EDGES + 255) / 256, 256>>>(esrc, edst);

    const int tgrid = (N_NODES + 63) / 64;
    const int agrid = (N_NODES + 7) / 8;   // 8 warps (nodes) per 256-thread block

    // layer 1
    k_transform<128><<<tgrid, 256, smem128>>>(x, W1, p_hw);
    k_agg<true><<<agrid, 256>>>(p_hw, b1, p_h);
    // layer 2
    k_transform<64><<<tgrid, 256, smem64>>>(p_h, W2, p_hw);
    k_agg<true><<<agrid, 256>>>(p_hw, b2, p_h);
    // layer 3
    k_transform<64><<<tgrid, 256, smem64>>>(p_h, W3, p_hw);
    k_agg<false><<<agrid, 256>>>(p_hw, b3, out);
}

// round 3
// speedup vs baseline: 1.0310x; 1.0310x over previous
#include <cuda_runtime.h>
#include <cuda_fp16.h>

#define N_NODES 100000
#define N_EDGES 1600000
#define IN_CH   128
#define HID     64

// ---------------- device scratch (no allocations allowed) ----------------
__device__ int    g_deg[N_NODES];
__device__ int    g_off[N_NODES + 1];
__device__ int    g_cursor[N_NODES];
__device__ int    g_ssrc[N_EDGES];
__device__ int    g_bsum[128];
__device__ int    g_boff[128];
__device__ __half g_hw[N_NODES * HID];   // transformed features (gather source, fp16)
__device__ float  g_h [N_NODES * HID];   // aggregated features (fp32)

// ---------------- CSR build ----------------
__global__ void k_hist(const int* __restrict__ dst) {
    int i = blockIdx.x * blockDim.x + threadIdx.x;
    if (i < N_EDGES) atomicAdd(&g_deg[dst[i]], 1);
}

__global__ void k_scan_blocks() {
    __shared__ int s[1024];
    int tid = threadIdx.x;
    int i = blockIdx.x * 1024 + tid;
    int v = (i < N_NODES) ? g_deg[i] : 0;
    s[tid] = v;
    __syncthreads();
    #pragma unroll
    for (int off = 1; off < 1024; off <<= 1) {
        int t = (tid >= off) ? s[tid - off] : 0;
        __syncthreads();
        s[tid] += t;
        __syncthreads();
    }
    if (i < N_NODES) g_off[i] = s[tid] - v;   // block-local exclusive
    if (tid == 1023) g_bsum[blockIdx.x] = s[1023];
}

// parallel exclusive scan over <=128 block sums (one 128-thread block)
__global__ void k_scan_top(int nb) {
    __shared__ int s[128];
    int tid = threadIdx.x;
    int v = (tid < nb) ? g_bsum[tid] : 0;
    s[tid] = v;
    __syncthreads();
    #pragma unroll
    for (int off = 1; off < 128; off <<= 1) {
        int t = (tid >= off) ? s[tid - off] : 0;
        __syncthreads();
        s[tid] += t;
        __syncthreads();
    }
    if (tid < nb) g_boff[tid] = s[tid] - v;   // exclusive
}

__global__ void k_scan_add() {
    int i = blockIdx.x * blockDim.x + threadIdx.x;
    if (i < N_NODES) {
        int o = g_off[i] + g_boff[i >> 10];
        g_off[i] = o;
        g_cursor[i] = o;
    }
    if (i == 0) g_off[N_NODES] = N_EDGES;
}

__global__ void k_scatter(const int* __restrict__ src, const int* __restrict__ dst) {
    int i = blockIdx.x * blockDim.x + threadIdx.x;
    if (i < N_EDGES) {
        int p = atomicAdd(&g_cursor[dst[i]], 1);
        g_ssrc[p] = src[i];
    }
}

// ---------------- dense transform: O[n,64] = X[n,K] @ W[K,64], O in fp16 ----
// 256 threads/block, 64 rows/block; each thread: 2 rows x 8 cols.
template <int K>
__global__ __launch_bounds__(256)
void k_transform(const float* __restrict__ X, const float* __restrict__ W,
                 __half* __restrict__ O) {
    extern __shared__ float sm[];
    float* sW = sm;               // K*64
    float* sX = sm + K * 64;      // 64*(K+1)  (padded rows: no bank conflicts)
    const int tid = threadIdx.x;

    for (int i = tid; i < K * 64; i += 256) sW[i] = W[i];

    int rowBase = blockIdx.x * 64;
    for (int i = tid; i < 64 * K; i += 256) {
        int r = i / K, k = i - r * K;
        int gr = rowBase + r;
        sX[r * (K + 1) + k] = (gr < N_NODES) ? X[gr * K + k] : 0.f;
    }
    __syncthreads();

    const int colq = (tid & 7) * 8;        // 8 contiguous output cols
    const int r0 = (tid >> 3) * 2;         // 2 rows
    const int r1 = r0 + 1;
    const float* x0 = &sX[r0 * (K + 1)];
    const float* x1 = &sX[r1 * (K + 1)];

    float a0[8], a1[8];
    #pragma unroll
    for (int j = 0; j < 8; j++) { a0[j] = 0.f; a1[j] = 0.f; }

    #pragma unroll 16
    for (int k = 0; k < K; k++) {
        float4 wA = *(const float4*)&sW[k * 64 + colq];
        float4 wB = *(const float4*)&sW[k * 64 + colq + 4];
        float p0 = x0[k];
        float p1 = x1[k];
        a0[0] += p0 * wA.x; a0[1] += p0 * wA.y; a0[2] += p0 * wA.z; a0[3] += p0 * wA.w;
        a0[4] += p0 * wB.x; a0[5] += p0 * wB.y; a0[6] += p0 * wB.z; a0[7] += p0 * wB.w;
        a1[0] += p1 * wA.x; a1[1] += p1 * wA.y; a1[2] += p1 * wA.z; a1[3] += p1 * wA.w;
        a1[4] += p1 * wB.x; a1[5] += p1 * wB.y; a1[6] += p1 * wB.z; a1[7] += p1 * wB.w;
    }

    // pack 8 fp32 -> 8 fp16 -> one 16B store per row (union-based reinterpret)
    union Pack { __half2 h[4]; uint4 u; };
    Pack p0u, p1u;
    p0u.h[0] = __floats2half2_rn(a0[0], a0[1]);
    p0u.h[1] = __floats2half2_rn(a0[2], a0[3]);
    p0u.h[2] = __floats2half2_rn(a0[4], a0[5]);
    p0u.h[3] = __floats2half2_rn(a0[6], a0[7]);
    p1u.h[0] = __floats2half2_rn(a1[0], a1[1]);
    p1u.h[1] = __floats2half2_rn(a1[2], a1[3]);
    p1u.h[2] = __floats2half2_rn(a1[4], a1[5]);
    p1u.h[3] = __floats2half2_rn(a1[6], a1[7]);

    int gr0 = rowBase + r0, gr1 = rowBase + r1;
    uint4* O4 = (uint4*)O;                 // 8 halves per uint4
    if (gr0 < N_NODES) O4[gr0 * 8 + (tid & 7)] = p0u.u;
    if (gr1 < N_NODES) O4[gr1 * 8 + (tid & 7)] = p1u.u;
}

// ---------------- CSR gather-sum aggregation: one warp per node -------------
// HW is fp16: one edge = 128B = a single L2 line across the warp.
template <bool RELU>
__global__ __launch_bounds__(256)
void k_agg(const __half* __restrict__ HW, const float* __restrict__ bias,
           float* __restrict__ O) {
    int warp = (blockIdx.x * blockDim.x + threadIdx.x) >> 5;
    int lane = threadIdx.x & 31;
    if (warp >= N_NODES) return;

    int start = g_off[warp];
    int end   = g_off[warp + 1];

    const __half2* __restrict__ hw2 = (const __half2*)HW;
    float2 a0 = {0.f, 0.f}, a1 = {0.f, 0.f}, a2 = {0.f, 0.f}, a3 = {0.f, 0.f};

    int e = start;
    for (; e + 4 <= end; e += 4) {
        int s0 = __ldg(&g_ssrc[e]);
        int s1 = __ldg(&g_ssrc[e + 1]);
        int s2 = __ldg(&g_ssrc[e + 2]);
        int s3 = __ldg(&g_ssrc[e + 3]);
        float2 v0 = __half22float2(__ldg(&hw2[s0 * 32 + lane]));
        float2 v1 = __half22float2(__ldg(&hw2[s1 * 32 + lane]));
        float2 v2 = __half22float2(__ldg(&hw2[s2 * 32 + lane]));
        float2 v3 = __half22float2(__ldg(&hw2[s3 * 32 + lane]));
        a0.x += v0.x; a0.y += v0.y;
        a1.x += v1.x; a1.y += v1.y;
        a2.x += v2.x; a2.y += v2.y;
        a3.x += v3.x; a3.y += v3.y;
    }
    for (; e < end; e++) {
        int s = __ldg(&g_ssrc[e]);
        float2 v = __half22float2(__ldg(&hw2[s * 32 + lane]));
        a0.x += v.x; a0.y += v.y;
    }

    float2 b = __ldg(&((const float2*)bias)[lane]);
    float rx = (a0.x + a1.x) + (a2.x + a3.x) + b.x;
    float ry = (a0.y + a1.y) + (a2.y + a3.y) + b.y;
    if (RELU) { rx = fmaxf(rx, 0.f); ry = fmaxf(ry, 0.f); }
    ((float2*)O)[warp * 32 + lane] = make_float2(rx, ry);
}

// ---------------- launch ----------------
extern "C" void kernel_launch(void* const* d_in, const int* in_sizes, int n_in,
                              void* d_out, int out_size) {
    const float* x    = (const float*)d_in[0];
    const int*   esrc = (const int*)  d_in[1];
    const int*   edst = (const int*)  d_in[2];
    const float* W1   = (const float*)d_in[3];
    const float* b1   = (const float*)d_in[4];
    const float* W2   = (const float*)d_in[5];
    const float* b2   = (const float*)d_in[6];
    const float* W3   = (const float*)d_in[7];
    const float* b3   = (const float*)d_in[8];
    float* out = (float*)d_out;

    void* p_hw_v; cudaGetSymbolAddress(&p_hw_v, g_hw);
    void* p_h_v;  cudaGetSymbolAddress(&p_h_v,  g_h);
    void* p_deg_v; cudaGetSymbolAddress(&p_deg_v, g_deg);
    __half* p_hw = (__half*)p_hw_v;
    float*  p_h  = (float*)p_h_v;

    const int smem128 = (128 * 64 + 64 * 129) * 4;   // 65,792 B
    const int smem64  = (64 * 64 + 64 * 65) * 4;     // 33,024 B
    cudaFuncSetAttribute(k_transform<128>, cudaFuncAttributeMaxDynamicSharedMemorySize, smem128);
    cudaFuncSetAttribute(k_transform<64>,  cudaFuncAttributeMaxDynamicSharedMemorySize, smem64);

    // ---- CSR build (per launch: deterministic work) ----
    cudaMemsetAsync(p_deg_v, 0, N_NODES * sizeof(int));
    k_hist<<<(N_EDGES + 255) / 256, 256>>>(edst);
    int nb = (N_NODES + 1023) / 1024;
    k_scan_blocks<<<nb, 1024>>>();
    k_scan_top<<<1, 128>>>(nb);
    k_scan_add<<<(N_NODES + 255) / 256, 256>>>();
    k_scatter<<<(N_EDGES + 255) / 256, 256>>>(esrc, edst);

    const int tgrid = (N_NODES + 63) / 64;
    const int agrid = (N_NODES + 7) / 8;   // 8 warps (nodes) per 256-thread block

    // layer 1
    k_transform<128><<<tgrid, 256, smem128>>>(x, W1, p_hw);
    k_agg<true><<<agrid, 256>>>(p_hw, b1, p_h);
    // layer 2
    k_transform<64><<<tgrid, 256, smem64>>>(p_h, W2, p_hw);
    k_agg<true><<<agrid, 256>>>(p_hw, b2, p_h);
    // layer 3
    k_transform<64><<<tgrid, 256, smem64>>>(p_h, W3, p_hw);
    k_agg<false><<<agrid, 256>>>(p_hw, b3, out);
}

// round 4
// speedup vs baseline: 1.7625x; 1.7094x over previous
#include <cuda_runtime.h>
#include <cuda_fp16.h>
#include <mma.h>

using namespace nvcuda;

#define N_NODES 100000
#define N_EDGES 1600000
#define IN_CH   128
#define HID     64

// ---------------- device scratch (no allocations allowed) ----------------
__device__ int    g_deg[N_NODES];
__device__ int    g_off[N_NODES + 1];
__device__ int    g_cursor[N_NODES];
__device__ int    g_ssrc[N_EDGES];
__device__ int    g_bsum[128];
__device__ int    g_boff[128];
__device__ __half g_hw[N_NODES * HID];   // transformed features (gather source, fp16)
__device__ float  g_h [N_NODES * HID];   // aggregated features (fp32)

// ---------------- CSR build ----------------
__global__ void k_hist(const int* __restrict__ dst) {
    int i = blockIdx.x * blockDim.x + threadIdx.x;
    if (i < N_EDGES) atomicAdd(&g_deg[dst[i]], 1);
}

__global__ void k_scan_blocks() {
    __shared__ int s[1024];
    int tid = threadIdx.x;
    int i = blockIdx.x * 1024 + tid;
    int v = (i < N_NODES) ? g_deg[i] : 0;
    s[tid] = v;
    __syncthreads();
    #pragma unroll
    for (int off = 1; off < 1024; off <<= 1) {
        int t = (tid >= off) ? s[tid - off] : 0;
        __syncthreads();
        s[tid] += t;
        __syncthreads();
    }
    if (i < N_NODES) g_off[i] = s[tid] - v;   // block-local exclusive
    if (tid == 1023) g_bsum[blockIdx.x] = s[1023];
}

// parallel exclusive scan over <=128 block sums (one 128-thread block)
__global__ void k_scan_top(int nb) {
    __shared__ int s[128];
    int tid = threadIdx.x;
    int v = (tid < nb) ? g_bsum[tid] : 0;
    s[tid] = v;
    __syncthreads();
    #pragma unroll
    for (int off = 1; off < 128; off <<= 1) {
        int t = (tid >= off) ? s[tid - off] : 0;
        __syncthreads();
        s[tid] += t;
        __syncthreads();
    }
    if (tid < nb) g_boff[tid] = s[tid] - v;   // exclusive
}

__global__ void k_scan_add() {
    int i = blockIdx.x * blockDim.x + threadIdx.x;
    if (i < N_NODES) {
        int o = g_off[i] + g_boff[i >> 10];
        g_off[i] = o;
        g_cursor[i] = o;
    }
    if (i == 0) g_off[N_NODES] = N_EDGES;
}

__global__ void k_scatter(const int* __restrict__ src, const int* __restrict__ dst) {
    int i = blockIdx.x * blockDim.x + threadIdx.x;
    if (i < N_EDGES) {
        int p = atomicAdd(&g_cursor[dst[i]], 1);
        g_ssrc[p] = src[i];
    }
}

// ---- tensor-core transform: O[n,64] = half(X[n,K]) @ half(W[K,64]) --------
// 128 threads (4 warps) per block, 64 rows/block.
// warp w computes rows [16w,16w+16) x all 64 cols via 4 wmma accumulators.
// smem layouts (halves): sA 64 x (K+16), sB K x 80; staging sC 64 x 80 floats
// (reuses the sA/sB region after a sync). All fragment pointers 32B-aligned.
template <int K>
__global__ __launch_bounds__(128)
void k_transform_mma(const float* __restrict__ X, const float* __restrict__ W,
                     __half* __restrict__ O) {
    extern __shared__ char smraw[];
    const int LDA = K + 16;
    const int LDB = 80;
    __half* sA = (__half*)smraw;              // 64*LDA halves
    __half* sB = sA + 64 * LDA;               // K*LDB halves
    float*  sC = (float*)smraw;               // 64*80 floats (reuse)

    const int tid  = threadIdx.x;
    const int warp = tid >> 5;
    const int rowBase = blockIdx.x * 64;

    // W (fp32 global) -> sB (half)
    for (int i = tid; i < K * 64; i += 128) {
        int r = i >> 6, c = i & 63;
        sB[r * LDB + c] = __float2half(W[i]);
    }
    // X (fp32 global) -> sA (half), zero-pad OOB rows
    for (int i = tid; i < 64 * K; i += 128) {
        int r = i / K, c = i - r * K;
        int gr = rowBase + r;
        sA[r * LDA + c] = (gr < N_NODES) ? __float2half(X[(size_t)gr * K + c])
                                         : __half(0.f);
    }
    __syncthreads();

    wmma::fragment<wmma::accumulator, 16, 16, 16, float> acc[4];
    #pragma unroll
    for (int j = 0; j < 4; j++) wmma::fill_fragment(acc[j], 0.f);

    #pragma unroll
    for (int k = 0; k < K; k += 16) {
        wmma::fragment<wmma::matrix_a, 16, 16, 16, __half, wmma::row_major> a;
        wmma::load_matrix_sync(a, sA + warp * 16 * LDA + k, LDA);
        #pragma unroll
        for (int j = 0; j < 4; j++) {
            wmma::fragment<wmma::matrix_b, 16, 16, 16, __half, wmma::row_major> b;
            wmma::load_matrix_sync(b, sB + k * LDB + j * 16, LDB);
            wmma::mma_sync(acc[j], a, b, acc[j]);
        }
    }
    __syncthreads();   // all warps done reading sA/sB

    #pragma unroll
    for (int j = 0; j < 4; j++)
        wmma::store_matrix_sync(sC + warp * 16 * 80 + j * 16, acc[j], 80,
                                wmma::mem_row_major);
    __syncthreads();

    // pack fp32 staging -> fp16 global, 16B stores
    for (int i = tid; i < 64 * 8; i += 128) {      // 64 rows x 8 quads
        int r = i >> 3, q = i & 7;
        int gr = rowBase + r;
        if (gr < N_NODES) {
            const float* src = &sC[r * 80 + q * 8];
            union { __half2 h[4]; uint4 u; } p;
            p.h[0] = __floats2half2_rn(src[0], src[1]);
            p.h[1] = __floats2half2_rn(src[2], src[3]);
            p.h[2] = __floats2half2_rn(src[4], src[5]);
            p.h[3] = __floats2half2_rn(src[6], src[7]);
            ((uint4*)O)[(size_t)gr * 8 + q] = p.u;
        }
    }
}

// ---------------- CSR gather-sum aggregation: one warp per node -------------
// HW is fp16: one edge = 128B = a single L2 line across the warp.
template <bool RELU>
__global__ __launch_bounds__(256)
void k_agg(const __half* __restrict__ HW, const float* __restrict__ bias,
           float* __restrict__ O) {
    int warp = (blockIdx.x * blockDim.x + threadIdx.x) >> 5;
    int lane = threadIdx.x & 31;
    if (warp >= N_NODES) return;

    int start = g_off[warp];
    int end   = g_off[warp + 1];

    const __half2* __restrict__ hw2 = (const __half2*)HW;
    float2 a0 = {0.f, 0.f}, a1 = {0.f, 0.f}, a2 = {0.f, 0.f}, a3 = {0.f, 0.f};

    int e = start;
    for (; e + 4 <= end; e += 4) {
        int s0 = __ldg(&g_ssrc[e]);
        int s1 = __ldg(&g_ssrc[e + 1]);
        int s2 = __ldg(&g_ssrc[e + 2]);
        int s3 = __ldg(&g_ssrc[e + 3]);
        float2 v0 = __half22float2(__ldg(&hw2[s0 * 32 + lane]));
        float2 v1 = __half22float2(__ldg(&hw2[s1 * 32 + lane]));
        float2 v2 = __half22float2(__ldg(&hw2[s2 * 32 + lane]));
        float2 v3 = __half22float2(__ldg(&hw2[s3 * 32 + lane]));
        a0.x += v0.x; a0.y += v0.y;
        a1.x += v1.x; a1.y += v1.y;
        a2.x += v2.x; a2.y += v2.y;
        a3.x += v3.x; a3.y += v3.y;
    }
    for (; e < end; e++) {
        int s = __ldg(&g_ssrc[e]);
        float2 v = __half22float2(__ldg(&hw2[s * 32 + lane]));
        a0.x += v.x; a0.y += v.y;
    }

    float2 b = __ldg(&((const float2*)bias)[lane]);
    float rx = (a0.x + a1.x) + (a2.x + a3.x) + b.x;
    float ry = (a0.y + a1.y) + (a2.y + a3.y) + b.y;
    if (RELU) { rx = fmaxf(rx, 0.f); ry = fmaxf(ry, 0.f); }
    ((float2*)O)[warp * 32 + lane] = make_float2(rx, ry);
}

// ---------------- launch ----------------
extern "C" void kernel_launch(void* const* d_in, const int* in_sizes, int n_in,
                              void* d_out, int out_size) {
    const float* x    = (const float*)d_in[0];
    const int*   esrc = (const int*)  d_in[1];
    const int*   edst = (const int*)  d_in[2];
    const float* W1   = (const float*)d_in[3];
    const float* b1   = (const float*)d_in[4];
    const float* W2   = (const float*)d_in[5];
    const float* b2   = (const float*)d_in[6];
    const float* W3   = (const float*)d_in[7];
    const float* b3   = (const float*)d_in[8];
    float* out = (float*)d_out;

    void* p_hw_v; cudaGetSymbolAddress(&p_hw_v, g_hw);
    void* p_h_v;  cudaGetSymbolAddress(&p_h_v,  g_h);
    void* p_deg_v; cudaGetSymbolAddress(&p_deg_v, g_deg);
    __half* p_hw = (__half*)p_hw_v;
    float*  p_h  = (float*)p_h_v;

    // dynamic smem: K=128 -> 64*144*2 + 128*80*2 = 38912 B ; K=64 -> 20480 B
    const int smem128 = 64 * (128 + 16) * 2 + 128 * 80 * 2;
    const int smem64  = 64 * (64 + 16) * 2 + 64 * 80 * 2;
    cudaFuncSetAttribute(k_transform_mma<128>, cudaFuncAttributeMaxDynamicSharedMemorySize, smem128);
    cudaFuncSetAttribute(k_transform_mma<64>,  cudaFuncAttributeMaxDynamicSharedMemorySize, smem64);

    // ---- CSR build (per launch: deterministic work) ----
    cudaMemsetAsync(p_deg_v, 0, N_NODES * sizeof(int));
    k_hist<<<(N_EDGES + 255) / 256, 256>>>(edst);
    int nb = (N_NODES + 1023) / 1024;
    k_scan_blocks<<<nb, 1024>>>();
    k_scan_top<<<1, 128>>>(nb);
    k_scan_add<<<(N_NODES + 255) / 256, 256>>>();
    k_scatter<<<(N_EDGES + 255) / 256, 256>>>(esrc, edst);

    const int tgrid = (N_NODES + 63) / 64;
    const int agrid = (N_NODES + 7) / 8;   // 8 warps (nodes) per 256-thread block

    // layer 1
    k_transform_mma<128><<<tgrid, 128, smem128>>>(x, W1, p_hw);
    k_agg<true><<<agrid, 256>>>(p_hw, b1, p_h);
    // layer 2
    k_transform_mma<64><<<tgrid, 128, smem64>>>(p_h, W2, p_hw);
    k_agg<true><<<agrid, 256>>>(p_hw, b2, p_h);
    // layer 3
    k_transform_mma<64><<<tgrid, 128, smem64>>>(p_h, W3, p_hw);
    k_agg<false><<<agrid, 256>>>(p_hw, b3, out);
}

// round 5
// speedup vs baseline: 1.8840x; 1.0689x over previous
#include <cuda_runtime.h>
#include <cuda_fp16.h>
#include <mma.h>

using namespace nvcuda;

#define N_NODES 100000
#define N_EDGES 1600000
#define IN_CH   128
#define HID     64

// ---------------- device scratch (no allocations allowed) ----------------
__device__ int    g_deg[N_NODES];
__device__ int    g_off[N_NODES + 1];
__device__ int    g_cursor[N_NODES];
__device__ int    g_ssrc[N_EDGES];
__device__ int    g_bsum[128];
__device__ int    g_boff[128];
__device__ __half g_hw[N_NODES * HID];    // gather table A (fp16)
__device__ __half g_hw2[N_NODES * HID];   // gather table B (fp16)

// ---------------- CSR build ----------------
__global__ void k_hist(const int* __restrict__ dst) {
    int i = blockIdx.x * blockDim.x + threadIdx.x;
    if (i < N_EDGES) atomicAdd(&g_deg[dst[i]], 1);
}

__global__ void k_scan_blocks() {
    __shared__ int s[1024];
    int tid = threadIdx.x;
    int i = blockIdx.x * 1024 + tid;
    int v = (i < N_NODES) ? g_deg[i] : 0;
    s[tid] = v;
    __syncthreads();
    #pragma unroll
    for (int off = 1; off < 1024; off <<= 1) {
        int t = (tid >= off) ? s[tid - off] : 0;
        __syncthreads();
        s[tid] += t;
        __syncthreads();
    }
    if (i < N_NODES) g_off[i] = s[tid] - v;   // block-local exclusive
    if (tid == 1023) g_bsum[blockIdx.x] = s[1023];
}

__global__ void k_scan_top(int nb) {
    __shared__ int s[128];
    int tid = threadIdx.x;
    int v = (tid < nb) ? g_bsum[tid] : 0;
    s[tid] = v;
    __syncthreads();
    #pragma unroll
    for (int off = 1; off < 128; off <<= 1) {
        int t = (tid >= off) ? s[tid - off] : 0;
        __syncthreads();
        s[tid] += t;
        __syncthreads();
    }
    if (tid < nb) g_boff[tid] = s[tid] - v;   // exclusive
}

__global__ void k_scan_add() {
    int i = blockIdx.x * blockDim.x + threadIdx.x;
    if (i < N_NODES) {
        int o = g_off[i] + g_boff[i >> 10];
        g_off[i] = o;
        g_cursor[i] = o;
    }
    if (i == 0) g_off[N_NODES] = N_EDGES;
}

__global__ void k_scatter(const int* __restrict__ src, const int* __restrict__ dst) {
    int i = blockIdx.x * blockDim.x + threadIdx.x;
    if (i < N_EDGES) {
        int p = atomicAdd(&g_cursor[dst[i]], 1);
        g_ssrc[p] = src[i];
    }
}

// ---- layer-1 tensor-core transform: O[n,64] = half(X[n,128]) @ half(W1) ----
template <int K>
__global__ __launch_bounds__(128)
void k_transform_mma(const float* __restrict__ X, const float* __restrict__ W,
                     __half* __restrict__ O) {
    extern __shared__ char smraw[];
    const int LDA = K + 16;
    const int LDB = 80;
    __half* sA = (__half*)smraw;              // 64*LDA halves
    __half* sB = sA + 64 * LDA;               // K*LDB halves
    float*  sC = (float*)smraw;               // 64*80 floats (reuse)

    const int tid  = threadIdx.x;
    const int warp = tid >> 5;
    const int rowBase = blockIdx.x * 64;

    for (int i = tid; i < K * 64; i += 128) {
        int r = i >> 6, c = i & 63;
        sB[r * LDB + c] = __float2half(W[i]);
    }
    for (int i = tid; i < 64 * K; i += 128) {
        int r = i / K, c = i - r * K;
        int gr = rowBase + r;
        sA[r * LDA + c] = (gr < N_NODES) ? __float2half(X[(size_t)gr * K + c])
                                         : __half(0.f);
    }
    __syncthreads();

    wmma::fragment<wmma::accumulator, 16, 16, 16, float> acc[4];
    #pragma unroll
    for (int j = 0; j < 4; j++) wmma::fill_fragment(acc[j], 0.f);

    #pragma unroll
    for (int k = 0; k < K; k += 16) {
        wmma::fragment<wmma::matrix_a, 16, 16, 16, __half, wmma::row_major> a;
        wmma::load_matrix_sync(a, sA + warp * 16 * LDA + k, LDA);
        #pragma unroll
        for (int j = 0; j < 4; j++) {
            wmma::fragment<wmma::matrix_b, 16, 16, 16, __half, wmma::row_major> b;
            wmma::load_matrix_sync(b, sB + k * LDB + j * 16, LDB);
            wmma::mma_sync(acc[j], a, b, acc[j]);
        }
    }
    __syncthreads();

    #pragma unroll
    for (int j = 0; j < 4; j++)
        wmma::store_matrix_sync(sC + warp * 16 * 80 + j * 16, acc[j], 80,
                                wmma::mem_row_major);
    __syncthreads();

    for (int i = tid; i < 64 * 8; i += 128) {
        int r = i >> 3, q = i & 7;
        int gr = rowBase + r;
        if (gr < N_NODES) {
            const float* src = &sC[r * 80 + q * 8];
            union { __half2 h[4]; uint4 u; } p;
            p.h[0] = __floats2half2_rn(src[0], src[1]);
            p.h[1] = __floats2half2_rn(src[2], src[3]);
            p.h[2] = __floats2half2_rn(src[4], src[5]);
            p.h[3] = __floats2half2_rn(src[6], src[7]);
            ((uint4*)O)[(size_t)gr * 8 + q] = p.u;
        }
    }
}

// ---- fused agg(+bias,relu) -> GEMM(W) -> fp16 table (layers 2 and 3) ------
// 256 threads / 8 warps per block, 64 nodes per block.
// Phase A: warp w aggregates nodes [8w, 8w+8) into sA (fp16, LDA=80).
// Phase B: warp w computes 16-row stripe (w>>1), 32-col half (w&1) via wmma.
__global__ __launch_bounds__(256)
void k_agg_transform(const __half* __restrict__ HW, const float* __restrict__ bias,
                     const float* __restrict__ W, __half* __restrict__ O) {
    extern __shared__ char smraw[];
    const int LDA = 80, LDB = 80, LDC = 80;
    __half* sA = (__half*)smraw;              // 64*80 halves
    __half* sB = sA + 64 * LDA;               // 64*80 halves
    float*  sC = (float*)smraw;               // 64*80 floats (overlay)

    const int tid  = threadIdx.x;
    const int warp = tid >> 5;
    const int lane = tid & 31;
    const int rowBase = blockIdx.x * 64;

    // load W -> sB (half)
    for (int i = tid; i < 64 * 64; i += 256) {
        int r = i >> 6, c = i & 63;
        sB[r * LDB + c] = __float2half(W[i]);
    }

    // Phase A: aggregate 8 nodes per warp
    const __half2* __restrict__ hw2 = (const __half2*)HW;
    float2 bb = __ldg(&((const float2*)bias)[lane]);
    #pragma unroll 1
    for (int i = 0; i < 8; i++) {
        int r  = warp * 8 + i;
        int gr = rowBase + r;
        float2 a0 = {0.f, 0.f}, a1 = {0.f, 0.f}, a2 = {0.f, 0.f}, a3 = {0.f, 0.f};
        if (gr < N_NODES) {
            int e   = g_off[gr];
            int end = g_off[gr + 1];
            for (; e + 4 <= end; e += 4) {
                int s0 = __ldg(&g_ssrc[e]);
                int s1 = __ldg(&g_ssrc[e + 1]);
                int s2 = __ldg(&g_ssrc[e + 2]);
                int s3 = __ldg(&g_ssrc[e + 3]);
                float2 v0 = __half22float2(__ldg(&hw2[s0 * 32 + lane]));
                float2 v1 = __half22float2(__ldg(&hw2[s1 * 32 + lane]));
                float2 v2 = __half22float2(__ldg(&hw2[s2 * 32 + lane]));
                float2 v3 = __half22float2(__ldg(&hw2[s3 * 32 + lane]));
                a0.x += v0.x; a0.y += v0.y;
                a1.x += v1.x; a1.y += v1.y;
                a2.x += v2.x; a2.y += v2.y;
                a3.x += v3.x; a3.y += v3.y;
            }
            for (; e < end; e++) {
                int s = __ldg(&g_ssrc[e]);
                float2 v = __half22float2(__ldg(&hw2[s * 32 + lane]));
                a0.x += v.x; a0.y += v.y;
            }
        }
        float rx = fmaxf((a0.x + a1.x) + (a2.x + a3.x) + bb.x, 0.f);
        float ry = fmaxf((a0.y + a1.y) + (a2.y + a3.y) + bb.y, 0.f);
        ((__half2*)(sA + r * LDA))[lane] = __floats2half2_rn(rx, ry);
    }
    __syncthreads();

    // Phase B: GEMM sA(64xK=64) @ sB(64x64)
    const int stripe  = warp >> 1;        // 0..3 (16-row stripe)
    const int colHalf = warp & 1;         // 0..1 (32-col half)
    wmma::fragment<wmma::accumulator, 16, 16, 16, float> acc[2];
    wmma::fill_fragment(acc[0], 0.f);
    wmma::fill_fragment(acc[1], 0.f);

    #pragma unroll
    for (int k = 0; k < 64; k += 16) {
        wmma::fragment<wmma::matrix_a, 16, 16, 16, __half, wmma::row_major> a;
        wmma::load_matrix_sync(a, sA + stripe * 16 * LDA + k, LDA);
        #pragma unroll
        for (int j = 0; j < 2; j++) {
            wmma::fragment<wmma::matrix_b, 16, 16, 16, __half, wmma::row_major> b;
            wmma::load_matrix_sync(b, sB + k * LDB + colHalf * 32 + j * 16, LDB);
            wmma::mma_sync(acc[j], a, b, acc[j]);
        }
    }
    __syncthreads();   // done reading sA/sB before sC overlay

    #pragma unroll
    for (int j = 0; j < 2; j++)
        wmma::store_matrix_sync(sC + stripe * 16 * LDC + colHalf * 32 + j * 16,
                                acc[j], LDC, wmma::mem_row_major);
    __syncthreads();

    // pack fp32 staging -> fp16 global
    for (int i = tid; i < 64 * 8; i += 256) {
        int r = i >> 3, q = i & 7;
        int gr = rowBase + r;
        if (gr < N_NODES) {
            const float* src = &sC[r * LDC + q * 8];
            union { __half2 h[4]; uint4 u; } p;
            p.h[0] = __floats2half2_rn(src[0], src[1]);
            p.h[1] = __floats2half2_rn(src[2], src[3]);
            p.h[2] = __floats2half2_rn(src[4], src[5]);
            p.h[3] = __floats2half2_rn(src[6], src[7]);
            ((uint4*)O)[(size_t)gr * 8 + q] = p.u;
        }
    }
}

// ---------------- final aggregation (no activation, fp32 out) ---------------
__global__ __launch_bounds__(256)
void k_agg_final(const __half* __restrict__ HW, const float* __restrict__ bias,
                 float* __restrict__ O) {
    int warp = (blockIdx.x * blockDim.x + threadIdx.x) >> 5;
    int lane = threadIdx.x & 31;
    if (warp >= N_NODES) return;

    int e   = g_off[warp];
    int end = g_off[warp + 1];

    const __half2* __restrict__ hw2 = (const __half2*)HW;
    float2 a0 = {0.f, 0.f}, a1 = {0.f, 0.f}, a2 = {0.f, 0.f}, a3 = {0.f, 0.f};
    for (; e + 4 <= end; e += 4) {
        int s0 = __ldg(&g_ssrc[e]);
        int s1 = __ldg(&g_ssrc[e + 1]);
        int s2 = __ldg(&g_ssrc[e + 2]);
        int s3 = __ldg(&g_ssrc[e + 3]);
        float2 v0 = __half22float2(__ldg(&hw2[s0 * 32 + lane]));
        float2 v1 = __half22float2(__ldg(&hw2[s1 * 32 + lane]));
        float2 v2 = __half22float2(__ldg(&hw2[s2 * 32 + lane]));
        float2 v3 = __half22float2(__ldg(&hw2[s3 * 32 + lane]));
        a0.x += v0.x; a0.y += v0.y;
        a1.x += v1.x; a1.y += v1.y;
        a2.x += v2.x; a2.y += v2.y;
        a3.x += v3.x; a3.y += v3.y;
    }
    for (; e < end; e++) {
        int s = __ldg(&g_ssrc[e]);
        float2 v = __half22float2(__ldg(&hw2[s * 32 + lane]));
        a0.x += v.x; a0.y += v.y;
    }

    float2 b = __ldg(&((const float2*)bias)[lane]);
    float rx = (a0.x + a1.x) + (a2.x + a3.x) + b.x;
    float ry = (a0.y + a1.y) + (a2.y + a3.y) + b.y;
    ((float2*)O)[warp * 32 + lane] = make_float2(rx, ry);
}

// ---------------- launch ----------------
extern "C" void kernel_launch(void* const* d_in, const int* in_sizes, int n_in,
                              void* d_out, int out_size) {
    const float* x    = (const float*)d_in[0];
    const int*   esrc = (const int*)  d_in[1];
    const int*   edst = (const int*)  d_in[2];
    const float* W1   = (const float*)d_in[3];
    const float* b1   = (const float*)d_in[4];
    const float* W2   = (const float*)d_in[5];
    const float* b2   = (const float*)d_in[6];
    const float* W3   = (const float*)d_in[7];
    const float* b3   = (const float*)d_in[8];
    float* out = (float*)d_out;

    void* p_hw_v;  cudaGetSymbolAddress(&p_hw_v,  g_hw);
    void* p_hw2_v; cudaGetSymbolAddress(&p_hw2_v, g_hw2);
    void* p_deg_v; cudaGetSymbolAddress(&p_deg_v, g_deg);
    __half* p_hw  = (__half*)p_hw_v;
    __half* p_hw2 = (__half*)p_hw2_v;

    // lazily-created side stream + fork/join events (host objects only)
    static cudaStream_t s2 = nullptr;
    static cudaEvent_t evFork = nullptr, evJoin = nullptr;
    if (!s2) {
        cudaStreamCreateWithFlags(&s2, cudaStreamNonBlocking);
        cudaEventCreateWithFlags(&evFork, cudaEventDisableTiming);
        cudaEventCreateWithFlags(&evJoin, cudaEventDisableTiming);
    }

    const int smem128 = 64 * (128 + 16) * 2 + 128 * 80 * 2;  // 38,912 B
    const int smemF   = 64 * 80 * 4;                          // 20,480 B
    cudaFuncSetAttribute(k_transform_mma<128>, cudaFuncAttributeMaxDynamicSharedMemorySize, smem128);
    cudaFuncSetAttribute(k_agg_transform,      cudaFuncAttributeMaxDynamicSharedMemorySize, smemF);

    const int tgrid = (N_NODES + 63) / 64;
    const int agrid = (N_NODES + 7) / 8;

    // ---- fork: CSR build on s2, layer-1 transform on main stream ----
    cudaEventRecord(evFork, 0);
    cudaStreamWaitEvent(s2, evFork, 0);

    cudaMemsetAsync(p_deg_v, 0, N_NODES * sizeof(int), s2);
    k_hist<<<(N_EDGES + 255) / 256, 256, 0, s2>>>(edst);
    int nb = (N_NODES + 1023) / 1024;
    k_scan_blocks<<<nb, 1024, 0, s2>>>();
    k_scan_top<<<1, 128, 0, s2>>>(nb);
    k_scan_add<<<(N_NODES + 255) / 256, 256, 0, s2>>>();
    k_scatter<<<(N_EDGES + 255) / 256, 256, 0, s2>>>(esrc, edst);
    cudaEventRecord(evJoin, s2);

    k_transform_mma<128><<<tgrid, 128, smem128>>>(x, W1, p_hw);

    cudaStreamWaitEvent(0, evJoin, 0);   // join before first aggregation

    // layer 2: agg(hw,+b1,relu) -> @W2 -> hw2
    k_agg_transform<<<tgrid, 256, smemF>>>(p_hw, b1, W2, p_hw2);
    // layer 3: agg(hw2,+b2,relu) -> @W3 -> hw
    k_agg_transform<<<tgrid, 256, smemF>>>(p_hw2, b2, W3, p_hw);
    // final: agg(hw) + b3 -> out (fp32)
    k_agg_final<<<agrid, 256>>>(p_hw, b3, out);
}

// round 6
// speedup vs baseline: 1.9487x; 1.0344x over previous
#include <cuda_runtime.h>
#include <cuda_fp16.h>
#include <mma.h>

using namespace nvcuda;

#define N_NODES 100000
#define N_EDGES 1600000
#define IN_CH   128
#define HID     64
#define SSRC_CAP (N_EDGES + 4 * N_NODES)

// ---------------- device scratch (no allocations allowed) ----------------
__device__ int    g_deg[N_NODES];
__device__ int    g_off[N_NODES];      // segment start per node (4-aligned)
__device__ int    g_cursor[N_NODES];
__device__ int    g_total;
__device__ int    g_ssrc[SSRC_CAP];
__device__ __half g_hw[N_NODES * HID];    // gather table A (fp16)
__device__ __half g_hw2[N_NODES * HID];   // gather table B (fp16)

// ---------------- CSR build ----------------
__global__ void k_hist(const int* __restrict__ dst) {
    int i = blockIdx.x * blockDim.x + threadIdx.x;
    if (i == 0) g_total = 0;
    if (i < N_EDGES) atomicAdd(&g_deg[dst[i]], 1);
}

// one-kernel segment assignment: block scan of padded degrees + atomic base.
// Segments are disjoint, 4-aligned, size = deg rounded up to 4 (pad unread).
__global__ __launch_bounds__(1024) void k_scan_assign() {
    __shared__ int wsum[32];
    __shared__ int blockBase;
    int tid = threadIdx.x, lane = tid & 31, wid = tid >> 5;
    int i = blockIdx.x * 1024 + tid;
    int deg = (i < N_NODES) ? g_deg[i] : 0;
    int pv = (deg + 3) & ~3;
    int incl = pv;
    #pragma unroll
    for (int o = 1; o < 32; o <<= 1) {
        int t = __shfl_up_sync(0xFFFFFFFFu, incl, o);
        if (lane >= o) incl += t;
    }
    if (lane == 31) wsum[wid] = incl;
    __syncthreads();
    if (wid == 0) {
        int s = wsum[lane];
        #pragma unroll
        for (int o = 1; o < 32; o <<= 1) {
            int t = __shfl_up_sync(0xFFFFFFFFu, s, o);
            if (lane >= o) s += t;
        }
        wsum[lane] = s;
        if (lane == 31) blockBase = atomicAdd(&g_total, s);
    }
    __syncthreads();
    int warpPre = (wid > 0) ? wsum[wid - 1] : 0;
    int off = blockBase + warpPre + incl - pv;
    if (i < N_NODES) { g_off[i] = off; g_cursor[i] = off; }
}

__global__ void k_scatter(const int* __restrict__ src, const int* __restrict__ dst) {
    int i = blockIdx.x * blockDim.x + threadIdx.x;
    if (i < N_EDGES) {
        int p = atomicAdd(&g_cursor[dst[i]], 1);
        g_ssrc[p] = src[i];
    }
}

// ---- layer-1 tensor-core transform: O[n,64] = half(X[n,128]) @ half(W1) ----
template <int K>
__global__ __launch_bounds__(128)
void k_transform_mma(const float* __restrict__ X, const float* __restrict__ W,
                     __half* __restrict__ O) {
    extern __shared__ char smraw[];
    const int LDA = K + 16;
    const int LDB = 80;
    __half* sA = (__half*)smraw;              // 64*LDA halves
    __half* sB = sA + 64 * LDA;               // K*LDB halves
    float*  sC = (float*)smraw;               // 64*80 floats (reuse)

    const int tid  = threadIdx.x;
    const int warp = tid >> 5;
    const int rowBase = blockIdx.x * 64;

    for (int i = tid; i < K * 64; i += 128) {
        int r = i >> 6, c = i & 63;
        sB[r * LDB + c] = __float2half(W[i]);
    }
    for (int i = tid; i < 64 * K; i += 128) {
        int r = i / K, c = i - r * K;
        int gr = rowBase + r;
        sA[r * LDA + c] = (gr < N_NODES) ? __float2half(X[(size_t)gr * K + c])
                                         : __half(0.f);
    }
    __syncthreads();

    wmma::fragment<wmma::accumulator, 16, 16, 16, float> acc[4];
    #pragma unroll
    for (int j = 0; j < 4; j++) wmma::fill_fragment(acc[j], 0.f);

    #pragma unroll
    for (int k = 0; k < K; k += 16) {
        wmma::fragment<wmma::matrix_a, 16, 16, 16, __half, wmma::row_major> a;
        wmma::load_matrix_sync(a, sA + warp * 16 * LDA + k, LDA);
        #pragma unroll
        for (int j = 0; j < 4; j++) {
            wmma::fragment<wmma::matrix_b, 16, 16, 16, __half, wmma::row_major> b;
            wmma::load_matrix_sync(b, sB + k * LDB + j * 16, LDB);
            wmma::mma_sync(acc[j], a, b, acc[j]);
        }
    }
    __syncthreads();

    #pragma unroll
    for (int j = 0; j < 4; j++)
        wmma::store_matrix_sync(sC + warp * 16 * 80 + j * 16, acc[j], 80,
                                wmma::mem_row_major);
    __syncthreads();

    for (int i = tid; i < 64 * 8; i += 128) {
        int r = i >> 3, q = i & 7;
        int gr = rowBase + r;
        if (gr < N_NODES) {
            const float* src = &sC[r * 80 + q * 8];
            union { __half2 h[4]; uint4 u; } p;
            p.h[0] = __floats2half2_rn(src[0], src[1]);
            p.h[1] = __floats2half2_rn(src[2], src[3]);
            p.h[2] = __floats2half2_rn(src[4], src[5]);
            p.h[3] = __floats2half2_rn(src[6], src[7]);
            ((uint4*)O)[(size_t)gr * 8 + q] = p.u;
        }
    }
}

// warp-wide gather-sum of one node's segment (int4 index loads, 4-aligned base)
__device__ __forceinline__ float2 gather_node(const __half2* __restrict__ hw2,
                                              int start, int deg, int lane) {
    float2 a0 = {0.f, 0.f}, a1 = {0.f, 0.f}, a2 = {0.f, 0.f}, a3 = {0.f, 0.f};
    const int4* idx4 = (const int4*)(g_ssrc + start);
    int n4 = deg >> 2;
    for (int t = 0; t < n4; t++) {
        int4 s = __ldg(&idx4[t]);
        float2 v0 = __half22float2(__ldg(&hw2[s.x * 32 + lane]));
        float2 v1 = __half22float2(__ldg(&hw2[s.y * 32 + lane]));
        float2 v2 = __half22float2(__ldg(&hw2[s.z * 32 + lane]));
        float2 v3 = __half22float2(__ldg(&hw2[s.w * 32 + lane]));
        a0.x += v0.x; a0.y += v0.y;
        a1.x += v1.x; a1.y += v1.y;
        a2.x += v2.x; a2.y += v2.y;
        a3.x += v3.x; a3.y += v3.y;
    }
    for (int e = start + (n4 << 2); e < start + deg; e++) {
        int s = __ldg(&g_ssrc[e]);
        float2 v = __half22float2(__ldg(&hw2[s * 32 + lane]));
        a0.x += v.x; a0.y += v.y;
    }
    return make_float2((a0.x + a1.x) + (a2.x + a3.x),
                       (a0.y + a1.y) + (a2.y + a3.y));
}

// ---- fused agg(+bias,relu) -> GEMM(W) -> fp16 table (layers 2 and 3) ------
__global__ __launch_bounds__(256)
void k_agg_transform(const __half* __restrict__ HW, const float* __restrict__ bias,
                     const float* __restrict__ W, __half* __restrict__ O) {
    extern __shared__ char smraw[];
    const int LDA = 80, LDB = 80, LDC = 80;
    __half* sA = (__half*)smraw;              // 64*80 halves
    __half* sB = sA + 64 * LDA;               // 64*80 halves
    float*  sC = (float*)smraw;               // 64*80 floats (overlay)

    const int tid  = threadIdx.x;
    const int warp = tid >> 5;
    const int lane = tid & 31;
    const int rowBase = blockIdx.x * 64;

    for (int i = tid; i < 64 * 64; i += 256) {
        int r = i >> 6, c = i & 63;
        sB[r * LDB + c] = __float2half(W[i]);
    }

    const __half2* __restrict__ hw2 = (const __half2*)HW;
    float2 bb = __ldg(&((const float2*)bias)[lane]);
    #pragma unroll 1
    for (int i = 0; i < 8; i++) {
        int r  = warp * 8 + i;
        int gr = rowBase + r;
        float2 s = {0.f, 0.f};
        if (gr < N_NODES) s = gather_node(hw2, g_off[gr], g_deg[gr], lane);
        float rx = fmaxf(s.x + bb.x, 0.f);
        float ry = fmaxf(s.y + bb.y, 0.f);
        ((__half2*)(sA + r * LDA))[lane] = __floats2half2_rn(rx, ry);
    }
    __syncthreads();

    const int stripe  = warp >> 1;
    const int colHalf = warp & 1;
    wmma::fragment<wmma::accumulator, 16, 16, 16, float> acc[2];
    wmma::fill_fragment(acc[0], 0.f);
    wmma::fill_fragment(acc[1], 0.f);

    #pragma unroll
    for (int k = 0; k < 64; k += 16) {
        wmma::fragment<wmma::matrix_a, 16, 16, 16, __half, wmma::row_major> a;
        wmma::load_matrix_sync(a, sA + stripe * 16 * LDA + k, LDA);
        #pragma unroll
        for (int j = 0; j < 2; j++) {
            wmma::fragment<wmma::matrix_b, 16, 16, 16, __half, wmma::row_major> b;
            wmma::load_matrix_sync(b, sB + k * LDB + colHalf * 32 + j * 16, LDB);
            wmma::mma_sync(acc[j], a, b, acc[j]);
        }
    }
    __syncthreads();

    #pragma unroll
    for (int j = 0; j < 2; j++)
        wmma::store_matrix_sync(sC + stripe * 16 * LDC + colHalf * 32 + j * 16,
                                acc[j], LDC, wmma::mem_row_major);
    __syncthreads();

    for (int i = tid; i < 64 * 8; i += 256) {
        int r = i >> 3, q = i & 7;
        int gr = rowBase + r;
        if (gr < N_NODES) {
            const float* src = &sC[r * LDC + q * 8];
            union { __half2 h[4]; uint4 u; } p;
            p.h[0] = __floats2half2_rn(src[0], src[1]);
            p.h[1] = __floats2half2_rn(src[2], src[3]);
            p.h[2] = __floats2half2_rn(src[4], src[5]);
            p.h[3] = __floats2half2_rn(src[6], src[7]);
            ((uint4*)O)[(size_t)gr * 8 + q] = p.u;
        }
    }
}

// ---------------- final aggregation (no activation, fp32 out) ---------------
__global__ __launch_bounds__(256)
void k_agg_final(const __half* __restrict__ HW, const float* __restrict__ bias,
                 float* __restrict__ O) {
    int node = (blockIdx.x * blockDim.x + threadIdx.x) >> 5;
    int lane = threadIdx.x & 31;
    if (node >= N_NODES) return;

    const __half2* __restrict__ hw2 = (const __half2*)HW;
    float2 s = gather_node(hw2, g_off[node], g_deg[node], lane);
    float2 b = __ldg(&((const float2*)bias)[lane]);
    ((float2*)O)[node * 32 + lane] = make_float2(s.x + b.x, s.y + b.y);
}

// ---------------- launch ----------------
extern "C" void kernel_launch(void* const* d_in, const int* in_sizes, int n_in,
                              void* d_out, int out_size) {
    const float* x    = (const float*)d_in[0];
    const int*   esrc = (const int*)  d_in[1];
    const int*   edst = (const int*)  d_in[2];
    const float* W1   = (const float*)d_in[3];
    const float* b1   = (const float*)d_in[4];
    const float* W2   = (const float*)d_in[5];
    const float* b2   = (const float*)d_in[6];
    const float* W3   = (const float*)d_in[7];
    const float* b3   = (const float*)d_in[8];
    float* out = (float*)d_out;

    void* p_hw_v;  cudaGetSymbolAddress(&p_hw_v,  g_hw);
    void* p_hw2_v; cudaGetSymbolAddress(&p_hw2_v, g_hw2);
    void* p_deg_v; cudaGetSymbolAddress(&p_deg_v, g_deg);
    __half* p_hw  = (__half*)p_hw_v;
    __half* p_hw2 = (__half*)p_hw2_v;

    static cudaStream_t s2 = nullptr;
    static cudaEvent_t evFork = nullptr, evJoin = nullptr;
    if (!s2) {
        cudaStreamCreateWithFlags(&s2, cudaStreamNonBlocking);
        cudaEventCreateWithFlags(&evFork, cudaEventDisableTiming);
        cudaEventCreateWithFlags(&evJoin, cudaEventDisableTiming);
    }

    const int smem128 = 64 * (128 + 16) * 2 + 128 * 80 * 2;  // 38,912 B
    const int smemF   = 64 * 80 * 4;                          // 20,480 B
    cudaFuncSetAttribute(k_transform_mma<128>, cudaFuncAttributeMaxDynamicSharedMemorySize, smem128);
    cudaFuncSetAttribute(k_agg_transform,      cudaFuncAttributeMaxDynamicSharedMemorySize, smemF);

    const int tgrid = (N_NODES + 63) / 64;
    const int agrid = (N_NODES + 7) / 8;

    // ---- fork: CSR build on s2, layer-1 transform on main stream ----
    cudaEventRecord(evFork, 0);
    cudaStreamWaitEvent(s2, evFork, 0);

    cudaMemsetAsync(p_deg_v, 0, N_NODES * sizeof(int), s2);
    k_hist<<<(N_EDGES + 255) / 256, 256, 0, s2>>>(edst);
    k_scan_assign<<<(N_NODES + 1023) / 1024, 1024, 0, s2>>>();
    k_scatter<<<(N_EDGES + 255) / 256, 256, 0, s2>>>(esrc, edst);
    cudaEventRecord(evJoin, s2);

    k_transform_mma<128><<<tgrid, 128, smem128>>>(x, W1, p_hw);

    cudaStreamWaitEvent(0, evJoin, 0);   // join before first aggregation

    // layer 2: agg(hw,+b1,relu) -> @W2 -> hw2
    k_agg_transform<<<tgrid, 256, smemF>>>(p_hw, b1, W2, p_hw2);
    // layer 3: agg(hw2,+b2,relu) -> @W3 -> hw
    k_agg_transform<<<tgrid, 256, smemF>>>(p_hw2, b2, W3, p_hw);
    // final: agg(hw) + b3 -> out (fp32)
    k_agg_final<<<agrid, 256>>>(p_hw, b3, out);
}